// round 2
// baseline (speedup 1.0000x reference)
#include <cuda_runtime.h>
#include <math_constants.h>

// Problem constants (fixed shapes from reference)
#define CC      20
#define HW_     (512 * 512)          // 262144 = 2^18
#define BATCH_  8
#define NPIX    (BATCH_ * HW_)       // 2,097,152 pixels
#define THREADS 256
#define PPT     4                    // pixels per thread (float4)

// Global accumulators for the 3 levels (sum of log p). Zeroed per launch.
__device__ double g_acc[3];

__global__ void tce_init_kernel() {
    if (threadIdx.x < 3) g_acc[threadIdx.x] = 0.0;
}

__global__ __launch_bounds__(THREADS)
void tce_main_kernel(const float* __restrict__ logits,
                     const int*   __restrict__ targets)
{
    const int q = (blockIdx.x * THREADS + threadIdx.x) * PPT;  // first pixel index
    const int b = q >> 18;           // q / HW_
    const int s = q & (HW_ - 1);     // q % HW_
    const float* base = logits + (size_t)b * CC * HW_ + s;

    // Load 4 consecutive pixels for all 20 channels (20 coalesced LDG.128 streams)
    float4 v[CC];
#pragma unroll
    for (int c = 0; c < CC; ++c)
        v[c] = *reinterpret_cast<const float4*>(base + (size_t)c * HW_);

    const int4 tg4 = *reinterpret_cast<const int4*>(targets + q);
    const int tgt[4] = {tg4.x, tg4.y, tg4.z, tg4.w};

    float a0 = 0.f, a1 = 0.f, a2 = 0.f;   // per-thread sums of log p per level

#pragma unroll
    for (int j = 0; j < 4; ++j) {
        // per-pixel max (softmax shift-invariant; matches reference to fp32 noise)
        float m = -CUDART_INF_F;
#pragma unroll
        for (int c = 0; c < CC; ++c)
            m = fmaxf(m, reinterpret_cast<const float*>(&v[c])[j]);

        const int t = tgt[j];
        float s0 = 0.f, s1 = 0.f, s2 = 0.f, s3 = 0.f, pt = 0.f;
#pragma unroll
        for (int c = 0; c < CC; ++c) {
            const float e = __expf(reinterpret_cast<const float*>(&v[c])[j] - m);
            if      (c < 5)  s0 += e;
            else if (c < 10) s1 += e;
            else if (c < 15) s2 += e;
            else             s3 += e;
            pt = (c == t) ? e : pt;        // predicated pick, no dynamic indexing
        }
        const float total = (s0 + s1) + (s2 + s3);
        const float g10   = (t < 10) ? (s0 + s1) : (s2 + s3);
        const float g5    = (t < 5) ? s0 : (t < 10) ? s1 : (t < 15) ? s2 : s3;

        const float inv = __fdividef(1.0f, total);

        float p0 = fminf(fmaxf(g10 * inv, 1e-7f), 0.9999999f);
        float p1 = fminf(fmaxf(g5  * inv, 1e-7f), 0.9999999f);
        float p2 = fminf(fmaxf(pt  * inv, 1e-7f), 0.9999999f);

        a0 += __logf(p0);
        a1 += __logf(p1);
        a2 += __logf(p2);
    }

    // ---- block reduction: warp shuffle -> shared -> one atomicAdd per level ----
#pragma unroll
    for (int off = 16; off > 0; off >>= 1) {
        a0 += __shfl_down_sync(0xFFFFFFFFu, a0, off);
        a1 += __shfl_down_sync(0xFFFFFFFFu, a1, off);
        a2 += __shfl_down_sync(0xFFFFFFFFu, a2, off);
    }

    __shared__ float sm0[THREADS / 32], sm1[THREADS / 32], sm2[THREADS / 32];
    const int lane = threadIdx.x & 31;
    const int wid  = threadIdx.x >> 5;
    if (lane == 0) { sm0[wid] = a0; sm1[wid] = a1; sm2[wid] = a2; }
    __syncthreads();

    if (wid == 0) {
        const int nw = THREADS / 32;
        float b0 = (lane < nw) ? sm0[lane] : 0.f;
        float b1 = (lane < nw) ? sm1[lane] : 0.f;
        float b2 = (lane < nw) ? sm2[lane] : 0.f;
#pragma unroll
        for (int off = 4; off > 0; off >>= 1) {
            b0 += __shfl_down_sync(0xFFFFFFFFu, b0, off);
            b1 += __shfl_down_sync(0xFFFFFFFFu, b1, off);
            b2 += __shfl_down_sync(0xFFFFFFFFu, b2, off);
        }
        if (lane == 0) {
            atomicAdd(&g_acc[0], (double)b0);
            atomicAdd(&g_acc[1], (double)b1);
            atomicAdd(&g_acc[2], (double)b2);
        }
    }
}

__global__ void tce_finalize_kernel(float* __restrict__ out, int out_size) {
    if (threadIdx.x != 0 || blockIdx.x != 0) return;
    const double n  = (double)NPIX;
    const double l0 = -g_acc[0] / n;
    const double l1 = -g_acc[1] / n;
    const double l2 = -g_acc[2] / n;
    const double tot = l0 + l1 + l2;

    if (out_size == 3) {               // levels only (fallback layout)
        out[0] = (float)l0; out[1] = (float)l1; out[2] = (float)l2;
    } else {                           // (loss, level_losses) flattened
        if (out_size > 0) out[0] = (float)tot;
        if (out_size > 1) out[1] = (float)l0;
        if (out_size > 2) out[2] = (float)l1;
        if (out_size > 3) out[3] = (float)l2;
        for (int i = 4; i < out_size; ++i) out[i] = 0.f;
    }
}

extern "C" void kernel_launch(void* const* d_in, const int* in_sizes, int n_in,
                              void* d_out, int out_size) {
    const float* logits  = (const float*)d_in[0];
    const int*   targets = (const int*)d_in[1];
    float*       out     = (float*)d_out;

    tce_init_kernel<<<1, 32>>>();

    const int grid = NPIX / (THREADS * PPT);   // 2048 blocks
    tce_main_kernel<<<grid, THREADS>>>(logits, targets);

    tce_finalize_kernel<<<1, 32>>>(out, out_size);
}